// round 8
// baseline (speedup 1.0000x reference)
#include <cuda_runtime.h>
#include <cuda_bf16.h>
#include <cuda_fp16.h>
#include <stdint.h>

#define NB 1024
#define NP 16
#define NH 256
// S-grid: 25x25 nodes over [0,1]^2 -> 625 rows, padded to 640 (10 tiles of 64)
#define GN 25
#define GC 24
#define SG_TILES 10
// bias grid: 257 nodes over [0,1], padded to 320 (5 tiles)
#define BGC 256
#define BG_TILES 5

__device__ float  g_Sf[4][640][12];       // raw S MLP on grid (fp32)
__device__ __half g_Gh[625 * 48];         // symmetrized, layer-packed (96B/node)
__device__ float  g_Bgrid[2][320][4];     // bias MLPs on 1-D grid

__device__ __forceinline__ float tanh_f32(float x) {
    float y; asm("tanh.approx.f32 %0, %1;" : "=f"(y) : "f"(x)); return y;
}
__device__ __forceinline__ uint32_t pack_bf16x2(float lo, float hi) {
    uint32_t r; asm("cvt.rn.bf16x2.f32 %0, %1, %2;" : "=r"(r) : "f"(hi), "f"(lo));
    return r;
}
__device__ __forceinline__ void ldsm4(uint32_t r[4], uint32_t addr) {
    asm volatile("ldmatrix.sync.aligned.m8n8.x4.shared.b16 {%0,%1,%2,%3}, [%4];"
        : "=r"(r[0]), "=r"(r[1]), "=r"(r[2]), "=r"(r[3]) : "r"(addr));
}
__device__ __forceinline__ void mma16816(float c[4],
    uint32_t a0, uint32_t a1, uint32_t a2, uint32_t a3,
    uint32_t b0, uint32_t b1) {
    asm volatile(
        "mma.sync.aligned.m16n8k16.row.col.f32.bf16.bf16.f32 "
        "{%0,%1,%2,%3},{%4,%5,%6,%7},{%8,%9},{%0,%1,%2,%3};"
        : "+f"(c[0]), "+f"(c[1]), "+f"(c[2]), "+f"(c[3])
        : "r"(a0), "r"(a1), "r"(a2), "r"(a3), "r"(b0), "r"(b1));
}

// -------------------- MLP grid-evaluation kernel (512 threads) -------------
struct __align__(16) SmemLayout {
    __nv_bfloat16 W1t[256][258];   // [n][k]
    __nv_bfloat16 h0[64][264];     // [row][k] padded for ldsm
    __nv_bfloat16 W2t[16][258];
    float red[16][32][16];         // GEMM2 partials per warp
    float b1s[256];
    float b2s[16];
};

__global__ void __launch_bounds__(512, 1) mlp_grid(
    const float* __restrict__ sW0, const float* __restrict__ sb0,
    const float* __restrict__ sW1, const float* __restrict__ sb1,
    const float* __restrict__ sW2, const float* __restrict__ sb2,
    const float* __restrict__ qW0, const float* __restrict__ qb0,
    const float* __restrict__ qW1, const float* __restrict__ qb1,
    const float* __restrict__ qW2, const float* __restrict__ qb2,
    const float* __restrict__ kW0, const float* __restrict__ kb0,
    const float* __restrict__ kW1, const float* __restrict__ kb1,
    const float* __restrict__ kW2, const float* __restrict__ kb2)
{
    extern __shared__ char smem_raw[];
    SmemLayout& S = *reinterpret_cast<SmemLayout*>(smem_raw);
    const int t = threadIdx.x;
    const int warp = t >> 5, lane = t & 31;
    const int g = lane >> 2, tg = lane & 3;
    const int mw = warp & 1, nw = warp >> 1;   // 2 x 8 warp tiling
    const int y = blockIdx.y;
    const int sgrid_mode = (y < 4);
    const int ntiles = sgrid_mode ? SG_TILES : BG_TILES;
    if ((int)blockIdx.x >= ntiles) return;
    const int out_valid = sgrid_mode ? 9 : 3;

    const float *W0g, *b0g, *b1g, *b2g;
    const float* w1src;
    if (y < 4) { W0g = sW0 + y * 512; b0g = sb0 + y * 256; b1g = sb1 + y * 256;
                 b2g = sb2 + y * 9; w1src = sW1 + y * 65536; }
    else if (y == 4) { W0g = qW0; b0g = qb0; b1g = qb1; b2g = qb2; w1src = qW1; }
    else { W0g = kW0; b0g = kb0; b1g = kb1; b2g = kb2; w1src = kW1; }

    // ---- inline weight conversion: fp32 [k][n] -> bf16 smem [n][k] ----
    {
        const int n = t & 255, kh = (t >> 8) * 128;
        #pragma unroll 4
        for (int it = 0; it < 128; it++)
            S.W1t[n][kh + it] = __float2bfloat16(w1src[(kh + it) * 256 + n]);
    }
    if (t < 256) {
        #pragma unroll
        for (int n = 0; n < 16; n++) {
            float v = 0.f;
            if (y < 4)       { if (n < 9) v = sW2[y * 2304 + t * 9 + n]; }
            else if (y == 4) { if (n < 3) v = qW2[t * 3 + n]; }
            else             { if (n < 3) v = kW2[t * 3 + n]; }
            S.W2t[n][t] = __float2bfloat16(v);
        }
        S.b1s[t] = b1g[t];
        if (t < 16) S.b2s[t] = (t < out_valid) ? b2g[t] : 0.f;
    }

    const int tile = blockIdx.x;
    const int row0 = tile * 64;

    // ---- h0 = tanh(x @ W0 + b0), 32 k-values per thread ----
    {
        int r = t >> 3, cb = (t & 7) * 32;
        int rg = row0 + r;
        float xj, xi;
        if (sgrid_mode) {
            int gA = rg / GN;
            xj = (float)gA * (1.f / (float)GC);
            xi = (float)(rg - gA * GN) * (1.f / (float)GC);
        } else { xj = (float)rg * (1.f / (float)BGC); xi = 0.f; }
        #pragma unroll
        for (int k = 0; k < 32; k += 2) {
            int kk = cb + k;
            float w0 = __ldg(&W0g[kk]),  w1 = __ldg(&W0g[kk + 1]);
            float u0 = sgrid_mode ? __ldg(&W0g[NH + kk])     : 0.f;
            float u1 = sgrid_mode ? __ldg(&W0g[NH + kk + 1]) : 0.f;
            float a0 = fmaf(xj, w0, fmaf(xi, u0, __ldg(&b0g[kk])));
            float a1 = fmaf(xj, w1, fmaf(xi, u1, __ldg(&b0g[kk + 1])));
            *reinterpret_cast<uint32_t*>(&S.h0[r][kk]) =
                pack_bf16x2(tanh_f32(a0), tanh_f32(a1));
        }
    }
    __syncthreads();

    const int a_r = (lane & 7) + ((lane & 8) ? 8 : 0);
    const int a_c = (lane & 16) ? 8 : 0;
    const uint32_t h0base = (uint32_t)__cvta_generic_to_shared(&S.h0[0][0]);

    // ---- GEMM1: rows mw*32..+31, cols nw*32..+31 per warp ----
    float acc[2][4][4];
    #pragma unroll
    for (int mt = 0; mt < 2; mt++)
        #pragma unroll
        for (int nt = 0; nt < 4; nt++)
            #pragma unroll
            for (int c = 0; c < 4; c++) acc[mt][nt][c] = 0.f;

    const int rbase = mw * 32;
    #pragma unroll 4
    for (int kt = 0; kt < 16; kt++) {
        uint32_t a[2][4];
        #pragma unroll
        for (int mt = 0; mt < 2; mt++) {
            uint32_t addr = h0base +
                (uint32_t)(((rbase + mt * 16 + a_r) * 264 + kt * 16 + a_c) * 2);
            ldsm4(a[mt], addr);
        }
        #pragma unroll
        for (int nt = 0; nt < 4; nt++) {
            int n = nw * 32 + nt * 8 + g;
            uint32_t b0 = *reinterpret_cast<const uint32_t*>(&S.W1t[n][kt * 16 + 2 * tg]);
            uint32_t b1 = *reinterpret_cast<const uint32_t*>(&S.W1t[n][kt * 16 + 2 * tg + 8]);
            mma16816(acc[0][nt], a[0][0], a[0][1], a[0][2], a[0][3], b0, b1);
            mma16816(acc[1][nt], a[1][0], a[1][1], a[1][2], a[1][3], b0, b1);
        }
    }

    // ---- epilogue1: +b1, tanh, pack into GEMM2 A-fragments ----
    uint32_t A2[2][4][2];
    #pragma unroll
    for (int nt = 0; nt < 4; nt++) {
        int c0 = nw * 32 + nt * 8 + 2 * tg;
        float bb0 = S.b1s[c0], bb1 = S.b1s[c0 + 1];
        #pragma unroll
        for (int mt = 0; mt < 2; mt++) {
            float v0 = tanh_f32(acc[mt][nt][0] + bb0);
            float v1 = tanh_f32(acc[mt][nt][1] + bb1);
            float v2 = tanh_f32(acc[mt][nt][2] + bb0);
            float v3 = tanh_f32(acc[mt][nt][3] + bb1);
            A2[mt][nt][0] = pack_bf16x2(v0, v1);
            A2[mt][nt][1] = pack_bf16x2(v2, v3);
        }
    }

    // ---- GEMM2: this warp's k-slice = cols nw*32..+31 ----
    float c2[2][2][4];
    #pragma unroll
    for (int mt = 0; mt < 2; mt++)
        #pragma unroll
        for (int nb = 0; nb < 2; nb++)
            #pragma unroll
            for (int c = 0; c < 4; c++) c2[mt][nb][c] = 0.f;

    #pragma unroll
    for (int kt2 = 0; kt2 < 2; kt2++) {
        #pragma unroll
        for (int mt = 0; mt < 2; mt++) {
            uint32_t a0 = A2[mt][2 * kt2][0],     a1 = A2[mt][2 * kt2][1];
            uint32_t a2 = A2[mt][2 * kt2 + 1][0], a3 = A2[mt][2 * kt2 + 1][1];
            #pragma unroll
            for (int nb = 0; nb < 2; nb++) {
                uint32_t b0 = *reinterpret_cast<const uint32_t*>(
                    &S.W2t[nb * 8 + g][nw * 32 + kt2 * 16 + 2 * tg]);
                uint32_t b1 = *reinterpret_cast<const uint32_t*>(
                    &S.W2t[nb * 8 + g][nw * 32 + kt2 * 16 + 2 * tg + 8]);
                mma16816(c2[mt][nb], a0, a1, a2, a3, b0, b1);
            }
        }
    }

    // ---- stage partials ----
    #pragma unroll
    for (int mt = 0; mt < 2; mt++)
        #pragma unroll
        for (int nb = 0; nb < 2; nb++)
            #pragma unroll
            for (int c = 0; c < 4; c++) {
                int rr = mt * 16 + g + ((c >> 1) & 1) * 8;
                int cc = nb * 8 + 2 * tg + (c & 1);
                S.red[warp][rr][cc] = c2[mt][nb][c];
            }
    __syncthreads();

    // ---- reduce over 8 k-slices, +b2, tanh, store ----
    {
        int r64 = t >> 3, cq = t & 7;
        int mw2 = r64 >> 5, r32 = r64 & 31;
        #pragma unroll
        for (int cc = 0; cc < 2; cc++) {
            int col = cq * 2 + cc;
            float s = S.b2s[col];
            #pragma unroll
            for (int nn = 0; nn < 8; nn++) s += S.red[nn * 2 + mw2][r32][col];
            s = tanh_f32(s);
            if (col < out_valid) {
                int row = row0 + r64;
                if (sgrid_mode) g_Sf[y][row][col] = s;
                else            g_Bgrid[y - 4][row][col] = s;
            }
        }
    }
}

// -------------------- symmetrize + layer-pack the S table ------------------
// G_l(u,v) = S_l(u,v) + S_l(v,u)^T ; packed as [node][layer][12] halves (96B/node)
__global__ void __launch_bounds__(256) sym_kernel() {
    int idx = blockIdx.x * 256 + threadIdx.x;
    if (idx >= 625 * 4) return;
    int node = idx >> 2, l = idx & 3;
    int u = node / GN, v = node - u * GN;
    const float* Sa = &g_Sf[l][u * GN + v][0];
    const float* Sb = &g_Sf[l][v * GN + u][0];
    __half* dst = g_Gh + (size_t)node * 48 + l * 12;
    #pragma unroll
    for (int a = 0; a < 3; a++)
        #pragma unroll
        for (int c = 0; c < 3; c++)
            dst[a * 3 + c] = __float2half(Sa[a * 3 + c] + Sb[c * 3 + a]);
    dst[9] = dst[10] = dst[11] = __float2half(0.f);
}

// -------------------- assemble: single-bilerp symplectic updates -----------
__device__ __forceinline__ void acc_corner(int node, float w, float A[4][9]) {
    const uint4* p = reinterpret_cast<const uint4*>(g_Gh + (size_t)node * 48);
    uint4 d[6];
    #pragma unroll
    for (int k = 0; k < 6; k++) d[k] = __ldg(&p[k]);
    const __half* h = reinterpret_cast<const __half*>(d);
    #pragma unroll
    for (int l = 0; l < 4; l++)
        #pragma unroll
        for (int c = 0; c < 9; c++)
            A[l][c] = fmaf(w, __half2float(h[l * 12 + c]), A[l][c]);
}

__global__ void __launch_bounds__(256) assemble_interp(
    const float* __restrict__ q, const float* __restrict__ p,
    const float* __restrict__ m, const float* __restrict__ dtp,
    float* __restrict__ out)
{
    __shared__ float qf[48], pf[48];
    __shared__ float fr[16]; __shared__ int cl[16];
    __shared__ float frB[16]; __shared__ int clB[16];
    const int b = blockIdx.x, t = threadIdx.x;
    if (t < 48) { qf[t] = q[b * 48 + t]; pf[t] = p[b * 48 + t]; }
    if (t < 16) {
        float mv = m[b * 16 + t];
        float u = mv * (float)GC; int c = (int)u; if (c > GC - 1) c = GC - 1;
        cl[t] = c; fr[t] = u - (float)c;
        float uB = mv * (float)BGC; int cB = (int)uB; if (cB > BGC - 1) cB = BGC - 1;
        clB[t] = cB; frB[t] = uB - (float)cB;
    }
    float dt = dtp[0];
    const float scale = dt * dt * dt;
    __syncthreads();

    const int i = t >> 4, j = t & 15;
    // effective M_ij = bilerp of G at (x=m_j, y=m_i)
    const int cu = cl[j], cv = cl[i];
    const float fu = fr[j], fv = fr[i];
    const float w00 = (1.f - fu) * (1.f - fv), w01 = (1.f - fu) * fv;
    const float w10 = fu * (1.f - fv),         w11 = fu * fv;
    const int n00 = cu * GN + cv;

    float A[4][9];
    #pragma unroll
    for (int l = 0; l < 4; l++)
        #pragma unroll
        for (int c = 0; c < 9; c++) A[l][c] = 0.f;
    acc_corner(n00,          w00, A);
    acc_corner(n00 + 1,      w01, A);
    acc_corner(n00 + GN,     w10, A);
    acc_corner(n00 + GN + 1, w11, A);

    #pragma unroll
    for (int l = 0; l < 4; l++) {
        const float* src = (l & 1) ? pf : qf;
        float*       dst = (l & 1) ? qf : pf;
        float sj0 = src[j * 3 + 0], sj1 = src[j * 3 + 1], sj2 = src[j * 3 + 2];
        float y0 = A[l][0] * sj0 + A[l][1] * sj1 + A[l][2] * sj2;
        float y1 = A[l][3] * sj0 + A[l][4] * sj1 + A[l][5] * sj2;
        float y2 = A[l][6] * sj0 + A[l][7] * sj1 + A[l][8] * sj2;
        #pragma unroll
        for (int off = 8; off; off >>= 1) {
            y0 += __shfl_xor_sync(0xffffffffu, y0, off);
            y1 += __shfl_xor_sync(0xffffffffu, y1, off);
            y2 += __shfl_xor_sync(0xffffffffu, y2, off);
        }
        if (j == 0) {
            dst[i * 3 + 0] += scale * y0;
            dst[i * 3 + 1] += scale * y1;
            dst[i * 3 + 2] += scale * y2;
        }
        __syncthreads();
    }

    if (t < 48) {
        int pi = t / 3, e = t - pi * 3;
        int c = clB[pi]; float f = frB[pi];
        float bq0 = g_Bgrid[0][c][e], bq1 = g_Bgrid[0][c + 1][e];
        float bp0 = g_Bgrid[1][c][e], bp1 = g_Bgrid[1][c + 1][e];
        out[b * 48 + t]           = qf[t] + (bq0 + f * (bq1 - bq0)) * scale;
        out[NB * 48 + b * 48 + t] = pf[t] + (bp0 + f * (bp1 - bp0)) * scale;
    }
}

// -------------------- launch ------------------------------------------------
extern "C" void kernel_launch(void* const* d_in, const int* in_sizes, int n_in,
                              void* d_out, int out_size) {
    const float* q   = (const float*)d_in[0];
    const float* p   = (const float*)d_in[1];
    const float* m   = (const float*)d_in[2];
    const float* dt  = (const float*)d_in[3];
    const float* sW0 = (const float*)d_in[4];
    const float* sb0 = (const float*)d_in[5];
    const float* sW1 = (const float*)d_in[6];
    const float* sb1 = (const float*)d_in[7];
    const float* sW2 = (const float*)d_in[8];
    const float* sb2 = (const float*)d_in[9];
    const float* qW0 = (const float*)d_in[10];
    const float* qb0 = (const float*)d_in[11];
    const float* qW1 = (const float*)d_in[12];
    const float* qb1 = (const float*)d_in[13];
    const float* qW2 = (const float*)d_in[14];
    const float* qb2 = (const float*)d_in[15];
    const float* kW0 = (const float*)d_in[16];
    const float* kb0 = (const float*)d_in[17];
    const float* kW1 = (const float*)d_in[18];
    const float* kb1 = (const float*)d_in[19];
    const float* kW2 = (const float*)d_in[20];
    const float* kb2 = (const float*)d_in[21];
    float* out = (float*)d_out;

    static bool once = false;
    if (!once) {
        cudaFuncSetAttribute(mlp_grid, cudaFuncAttributeMaxDynamicSharedMemorySize,
                             (int)sizeof(SmemLayout));
        once = true;
    }
    {
        dim3 grid(SG_TILES, 6);
        mlp_grid<<<grid, 512, sizeof(SmemLayout)>>>(
            sW0, sb0, sW1, sb1, sW2, sb2,
            qW0, qb0, qW1, qb1, qW2, qb2,
            kW0, kb0, kW1, kb1, kW2, kb2);
    }
    sym_kernel<<<10, 256>>>();
    assemble_interp<<<NB, 256>>>(q, p, m, dt, out);
}

// round 9
// speedup vs baseline: 1.2390x; 1.2390x over previous
#include <cuda_runtime.h>
#include <cuda_bf16.h>
#include <cuda_fp16.h>
#include <stdint.h>

#define NB 1024
#define NP 16
#define NH 256
#define GN 25
#define GC 24
#define SG_TILES 10
#define BGC 256
#define BG_TILES 5

__device__ float  g_SfP[2][4][640][12];   // partial GEMM2 sums, per N-partition
__device__ float  g_BgP[2][2][320][4];    // partial bias-net sums
__device__ __half g_Gh[625 * 48];         // symmetrized, layer-packed (96B/node)
__device__ float  g_Bgrid[2][320][4];     // finalized bias tables

__device__ __forceinline__ float tanh_f32(float x) {
    float y; asm("tanh.approx.f32 %0, %1;" : "=f"(y) : "f"(x)); return y;
}
__device__ __forceinline__ uint32_t pack_bf16x2(float lo, float hi) {
    uint32_t r; asm("cvt.rn.bf16x2.f32 %0, %1, %2;" : "=r"(r) : "f"(hi), "f"(lo));
    return r;
}
__device__ __forceinline__ void ldsm4(uint32_t r[4], uint32_t addr) {
    asm volatile("ldmatrix.sync.aligned.m8n8.x4.shared.b16 {%0,%1,%2,%3}, [%4];"
        : "=r"(r[0]), "=r"(r[1]), "=r"(r[2]), "=r"(r[3]) : "r"(addr));
}
__device__ __forceinline__ void mma16816(float c[4],
    uint32_t a0, uint32_t a1, uint32_t a2, uint32_t a3,
    uint32_t b0, uint32_t b1) {
    asm volatile(
        "mma.sync.aligned.m16n8k16.row.col.f32.bf16.bf16.f32 "
        "{%0,%1,%2,%3},{%4,%5,%6,%7},{%8,%9},{%0,%1,%2,%3};"
        : "+f"(c[0]), "+f"(c[1]), "+f"(c[2]), "+f"(c[3])
        : "r"(a0), "r"(a1), "r"(a2), "r"(a3), "r"(b0), "r"(b1));
}

// -------------------- MLP grid-evaluation (N-split, 256 threads) -----------
struct __align__(16) SmemLayout {
    __nv_bfloat16 W1t[128][258];   // [n_local][k]
    __nv_bfloat16 h0[64][264];     // [row][k] padded for ldsm
    __nv_bfloat16 W2t[16][258];    // [n][k_local] (128 valid)
    float red[8][32][16];
    float b1s[128];
    float b0s[256];
    float W0s[2][256];
    float mjs[64];
    float mis[64];
};

__global__ void __launch_bounds__(256, 1) mlp_grid(
    const float* __restrict__ sW0, const float* __restrict__ sb0,
    const float* __restrict__ sW1, const float* __restrict__ sb1,
    const float* __restrict__ sW2,
    const float* __restrict__ qW0, const float* __restrict__ qb0,
    const float* __restrict__ qW1, const float* __restrict__ qb1,
    const float* __restrict__ qW2,
    const float* __restrict__ kW0, const float* __restrict__ kb0,
    const float* __restrict__ kW1, const float* __restrict__ kb1,
    const float* __restrict__ kW2)
{
    extern __shared__ char smem_raw[];
    SmemLayout& S = *reinterpret_cast<SmemLayout*>(smem_raw);
    const int t = threadIdx.x;
    const int warp = t >> 5, lane = t & 31;
    const int g = lane >> 2, tg = lane & 3;
    const int mw = warp & 1, nw = warp >> 1;   // 2 x 4 warp tiling
    const int y = blockIdx.y;
    const int ns = blockIdx.z;                  // N-partition 0/1
    const int sgrid_mode = (y < 4);
    const int ntiles = sgrid_mode ? SG_TILES : BG_TILES;
    if ((int)blockIdx.x >= ntiles) return;
    const int out_valid = sgrid_mode ? 9 : 3;

    const float *W0g, *b0g, *b1g, *w2src;
    const float* w1src;
    if (y < 4) { W0g = sW0 + y * 512; b0g = sb0 + y * 256; b1g = sb1 + y * 256;
                 w2src = sW2 + y * 2304; w1src = sW1 + y * 65536; }
    else if (y == 4) { W0g = qW0; b0g = qb0; b1g = qb1; w2src = qW2; w1src = qW1; }
    else { W0g = kW0; b0g = kb0; b1g = kb1; w2src = kW2; w1src = kW1; }

    // ---- weight conversion: fp32 [k][n] -> bf16 smem [n_local][k] ----
    {
        const int n = t & 127, kh = (t >> 7) * 128;
        const int ng = ns * 128 + n;
        for (int it = 0; it < 128; it++)
            S.W1t[n][kh + it] = __float2bfloat16(w1src[(kh + it) * 256 + ng]);
    }
    if (t < 128) {
        int kg = ns * 128 + t;
        #pragma unroll
        for (int n = 0; n < 16; n++) {
            float v = 0.f;
            if (sgrid_mode) { if (n < 9) v = w2src[kg * 9 + n]; }
            else            { if (n < 3) v = w2src[kg * 3 + n]; }
            S.W2t[n][t] = __float2bfloat16(v);
        }
        S.b1s[t] = b1g[ns * 128 + t];
    }
    S.b0s[t] = b0g[t];
    S.W0s[0][t] = W0g[t];
    S.W0s[1][t] = sgrid_mode ? W0g[NH + t] : 0.f;

    const int tile = blockIdx.x;
    const int row0 = tile * 64;
    if (t < 64) {
        int rg = row0 + t;
        float xj, xi;
        if (sgrid_mode) {
            int gA = rg / GN;
            xj = (float)gA * (1.f / (float)GC);
            xi = (float)(rg - gA * GN) * (1.f / (float)GC);
        } else { xj = (float)rg * (1.f / (float)BGC); xi = 0.f; }
        S.mjs[t] = xj; S.mis[t] = xi;
    }
    __syncthreads();

    // ---- h0 = tanh(x @ W0 + b0), full K=256 ----
    {
        int r = t >> 2, cb = (t & 3) * 64;
        float xj = S.mjs[r], xi = S.mis[r];
        #pragma unroll
        for (int k = 0; k < 64; k += 2) {
            int kk = cb + k;
            float a0 = fmaf(xj, S.W0s[0][kk],   fmaf(xi, S.W0s[1][kk],   S.b0s[kk]));
            float a1 = fmaf(xj, S.W0s[0][kk+1], fmaf(xi, S.W0s[1][kk+1], S.b0s[kk+1]));
            *reinterpret_cast<uint32_t*>(&S.h0[r][kk]) =
                pack_bf16x2(tanh_f32(a0), tanh_f32(a1));
        }
    }
    __syncthreads();

    const int a_r = (lane & 7) + ((lane & 8) ? 8 : 0);
    const int a_c = (lane & 16) ? 8 : 0;
    const uint32_t h0base = (uint32_t)__cvta_generic_to_shared(&S.h0[0][0]);

    // ---- GEMM1: rows mw*32..+31, cols nw*32..+31 (local) per warp ----
    float acc[2][4][4];
    #pragma unroll
    for (int mt = 0; mt < 2; mt++)
        #pragma unroll
        for (int nt = 0; nt < 4; nt++)
            #pragma unroll
            for (int c = 0; c < 4; c++) acc[mt][nt][c] = 0.f;

    const int rbase = mw * 32;
    #pragma unroll 4
    for (int kt = 0; kt < 16; kt++) {
        uint32_t a[2][4];
        #pragma unroll
        for (int mt = 0; mt < 2; mt++) {
            uint32_t addr = h0base +
                (uint32_t)(((rbase + mt * 16 + a_r) * 264 + kt * 16 + a_c) * 2);
            ldsm4(a[mt], addr);
        }
        #pragma unroll
        for (int nt = 0; nt < 4; nt++) {
            int n = nw * 32 + nt * 8 + g;
            uint32_t b0 = *reinterpret_cast<const uint32_t*>(&S.W1t[n][kt * 16 + 2 * tg]);
            uint32_t b1 = *reinterpret_cast<const uint32_t*>(&S.W1t[n][kt * 16 + 2 * tg + 8]);
            mma16816(acc[0][nt], a[0][0], a[0][1], a[0][2], a[0][3], b0, b1);
            mma16816(acc[1][nt], a[1][0], a[1][1], a[1][2], a[1][3], b0, b1);
        }
    }

    // ---- epilogue1: +b1, tanh, pack into GEMM2 A-fragments ----
    uint32_t A2[2][4][2];
    #pragma unroll
    for (int nt = 0; nt < 4; nt++) {
        int c0 = nw * 32 + nt * 8 + 2 * tg;
        float bb0 = S.b1s[c0], bb1 = S.b1s[c0 + 1];
        #pragma unroll
        for (int mt = 0; mt < 2; mt++) {
            float v0 = tanh_f32(acc[mt][nt][0] + bb0);
            float v1 = tanh_f32(acc[mt][nt][1] + bb1);
            float v2 = tanh_f32(acc[mt][nt][2] + bb0);
            float v3 = tanh_f32(acc[mt][nt][3] + bb1);
            A2[mt][nt][0] = pack_bf16x2(v0, v1);
            A2[mt][nt][1] = pack_bf16x2(v2, v3);
        }
    }

    // ---- GEMM2: this warp's k-slice = local cols nw*32..+31 ----
    float c2[2][2][4];
    #pragma unroll
    for (int mt = 0; mt < 2; mt++)
        #pragma unroll
        for (int nb = 0; nb < 2; nb++)
            #pragma unroll
            for (int c = 0; c < 4; c++) c2[mt][nb][c] = 0.f;

    #pragma unroll
    for (int kt2 = 0; kt2 < 2; kt2++) {
        #pragma unroll
        for (int mt = 0; mt < 2; mt++) {
            uint32_t a0 = A2[mt][2 * kt2][0],     a1 = A2[mt][2 * kt2][1];
            uint32_t a2 = A2[mt][2 * kt2 + 1][0], a3 = A2[mt][2 * kt2 + 1][1];
            #pragma unroll
            for (int nb = 0; nb < 2; nb++) {
                uint32_t b0 = *reinterpret_cast<const uint32_t*>(
                    &S.W2t[nb * 8 + g][nw * 32 + kt2 * 16 + 2 * tg]);
                uint32_t b1 = *reinterpret_cast<const uint32_t*>(
                    &S.W2t[nb * 8 + g][nw * 32 + kt2 * 16 + 2 * tg + 8]);
                mma16816(c2[mt][nb], a0, a1, a2, a3, b0, b1);
            }
        }
    }

    // ---- stage partials ----
    #pragma unroll
    for (int mt = 0; mt < 2; mt++)
        #pragma unroll
        for (int nb = 0; nb < 2; nb++)
            #pragma unroll
            for (int c = 0; c < 4; c++) {
                int rr = mt * 16 + g + ((c >> 1) & 1) * 8;
                int cc = nb * 8 + 2 * tg + (c & 1);
                S.red[warp][rr][cc] = c2[mt][nb][c];
            }
    __syncthreads();

    // ---- reduce over 4 k-slices, store RAW partial (tanh+b2 in sym) ----
    {
        int r64 = t >> 2, cq = t & 3;
        int mw2 = r64 >> 5, r32 = r64 & 31;
        #pragma unroll
        for (int cc = 0; cc < 4; cc++) {
            int col = cq * 4 + cc;
            float s = 0.f;
            #pragma unroll
            for (int nn = 0; nn < 4; nn++) s += S.red[nn * 2 + mw2][r32][col];
            if (col < out_valid) {
                int row = row0 + r64;
                if (sgrid_mode) g_SfP[ns][y][row][col] = s;
                else            g_BgP[ns][y - 4][row][col] = s;
            }
        }
    }
}

// -------------------- finalize: combine partitions, +b2, tanh, symmetrize --
__global__ void __launch_bounds__(256) sym_kernel(
    const float* __restrict__ sb2, const float* __restrict__ qb2,
    const float* __restrict__ kb2)
{
    int idx = blockIdx.x * 256 + threadIdx.x;
    if (idx < 625 * 4) {
        int node = idx >> 2, l = idx & 3;
        int u = node / GN, v = node - u * GN;
        int na = u * GN + v, nb = v * GN + u;
        const float* A0 = &g_SfP[0][l][na][0];
        const float* A1 = &g_SfP[1][l][na][0];
        const float* B0 = &g_SfP[0][l][nb][0];
        const float* B1 = &g_SfP[1][l][nb][0];
        const float* b2 = sb2 + l * 9;
        __half* dst = g_Gh + (size_t)node * 48 + l * 12;
        #pragma unroll
        for (int a = 0; a < 3; a++)
            #pragma unroll
            for (int c = 0; c < 3; c++) {
                float fa = tanh_f32(A0[a * 3 + c] + A1[a * 3 + c] + b2[a * 3 + c]);
                float fb = tanh_f32(B0[c * 3 + a] + B1[c * 3 + a] + b2[c * 3 + a]);
                dst[a * 3 + c] = __float2half(fa + fb);
            }
        dst[9] = dst[10] = dst[11] = __float2half(0.f);
    } else {
        int k = idx - 2500;
        if (k < 640) {
            int net = k >= 320, node = k - net * 320;
            const float* b2 = net ? kb2 : qb2;
            #pragma unroll
            for (int e = 0; e < 3; e++)
                g_Bgrid[net][node][e] =
                    tanh_f32(g_BgP[0][net][node][e] + g_BgP[1][net][node][e] + b2[e]);
        }
    }
}

// -------------------- assemble: single-bilerp symplectic updates -----------
__device__ __forceinline__ void acc_corner(int node, float w, float A[4][9]) {
    const uint4* p = reinterpret_cast<const uint4*>(g_Gh + (size_t)node * 48);
    uint4 d[6];
    #pragma unroll
    for (int k = 0; k < 6; k++) d[k] = __ldg(&p[k]);
    const __half* h = reinterpret_cast<const __half*>(d);
    #pragma unroll
    for (int l = 0; l < 4; l++)
        #pragma unroll
        for (int c = 0; c < 9; c++)
            A[l][c] = fmaf(w, __half2float(h[l * 12 + c]), A[l][c]);
}

__global__ void __launch_bounds__(256) assemble_interp(
    const float* __restrict__ q, const float* __restrict__ p,
    const float* __restrict__ m, const float* __restrict__ dtp,
    float* __restrict__ out)
{
    __shared__ float qf[48], pf[48];
    __shared__ float fr[16]; __shared__ int cl[16];
    __shared__ float frB[16]; __shared__ int clB[16];
    const int b = blockIdx.x, t = threadIdx.x;
    if (t < 48) { qf[t] = q[b * 48 + t]; pf[t] = p[b * 48 + t]; }
    if (t < 16) {
        float mv = m[b * 16 + t];
        float u = mv * (float)GC; int c = (int)u; if (c > GC - 1) c = GC - 1;
        cl[t] = c; fr[t] = u - (float)c;
        float uB = mv * (float)BGC; int cB = (int)uB; if (cB > BGC - 1) cB = BGC - 1;
        clB[t] = cB; frB[t] = uB - (float)cB;
    }
    float dt = dtp[0];
    const float scale = dt * dt * dt;
    __syncthreads();

    const int i = t >> 4, j = t & 15;
    const int cu = cl[j], cv = cl[i];
    const float fu = fr[j], fv = fr[i];
    const float w00 = (1.f - fu) * (1.f - fv), w01 = (1.f - fu) * fv;
    const float w10 = fu * (1.f - fv),         w11 = fu * fv;
    const int n00 = cu * GN + cv;

    float A[4][9];
    #pragma unroll
    for (int l = 0; l < 4; l++)
        #pragma unroll
        for (int c = 0; c < 9; c++) A[l][c] = 0.f;
    acc_corner(n00,          w00, A);
    acc_corner(n00 + 1,      w01, A);
    acc_corner(n00 + GN,     w10, A);
    acc_corner(n00 + GN + 1, w11, A);

    #pragma unroll
    for (int l = 0; l < 4; l++) {
        const float* src = (l & 1) ? pf : qf;
        float*       dst = (l & 1) ? qf : pf;
        float sj0 = src[j * 3 + 0], sj1 = src[j * 3 + 1], sj2 = src[j * 3 + 2];
        float y0 = A[l][0] * sj0 + A[l][1] * sj1 + A[l][2] * sj2;
        float y1 = A[l][3] * sj0 + A[l][4] * sj1 + A[l][5] * sj2;
        float y2 = A[l][6] * sj0 + A[l][7] * sj1 + A[l][8] * sj2;
        #pragma unroll
        for (int off = 8; off; off >>= 1) {
            y0 += __shfl_xor_sync(0xffffffffu, y0, off);
            y1 += __shfl_xor_sync(0xffffffffu, y1, off);
            y2 += __shfl_xor_sync(0xffffffffu, y2, off);
        }
        if (j == 0) {
            dst[i * 3 + 0] += scale * y0;
            dst[i * 3 + 1] += scale * y1;
            dst[i * 3 + 2] += scale * y2;
        }
        __syncthreads();
    }

    if (t < 48) {
        int pi = t / 3, e = t - pi * 3;
        int c = clB[pi]; float f = frB[pi];
        float bq0 = g_Bgrid[0][c][e], bq1 = g_Bgrid[0][c + 1][e];
        float bp0 = g_Bgrid[1][c][e], bp1 = g_Bgrid[1][c + 1][e];
        out[b * 48 + t]           = qf[t] + (bq0 + f * (bq1 - bq0)) * scale;
        out[NB * 48 + b * 48 + t] = pf[t] + (bp0 + f * (bp1 - bp0)) * scale;
    }
}

// -------------------- launch ------------------------------------------------
extern "C" void kernel_launch(void* const* d_in, const int* in_sizes, int n_in,
                              void* d_out, int out_size) {
    const float* q   = (const float*)d_in[0];
    const float* p   = (const float*)d_in[1];
    const float* m   = (const float*)d_in[2];
    const float* dt  = (const float*)d_in[3];
    const float* sW0 = (const float*)d_in[4];
    const float* sb0 = (const float*)d_in[5];
    const float* sW1 = (const float*)d_in[6];
    const float* sb1 = (const float*)d_in[7];
    const float* sW2 = (const float*)d_in[8];
    const float* sb2 = (const float*)d_in[9];
    const float* qW0 = (const float*)d_in[10];
    const float* qb0 = (const float*)d_in[11];
    const float* qW1 = (const float*)d_in[12];
    const float* qb1 = (const float*)d_in[13];
    const float* qW2 = (const float*)d_in[14];
    const float* qb2 = (const float*)d_in[15];
    const float* kW0 = (const float*)d_in[16];
    const float* kb0 = (const float*)d_in[17];
    const float* kW1 = (const float*)d_in[18];
    const float* kb1 = (const float*)d_in[19];
    const float* kW2 = (const float*)d_in[20];
    const float* kb2 = (const float*)d_in[21];
    float* out = (float*)d_out;

    static bool once = false;
    if (!once) {
        cudaFuncSetAttribute(mlp_grid, cudaFuncAttributeMaxDynamicSharedMemorySize,
                             (int)sizeof(SmemLayout));
        once = true;
    }
    {
        dim3 grid(SG_TILES, 6, 2);
        mlp_grid<<<grid, 256, sizeof(SmemLayout)>>>(
            sW0, sb0, sW1, sb1, sW2,
            qW0, qb0, qW1, qb1, qW2,
            kW0, kb0, kW1, kb1, kW2);
    }
    sym_kernel<<<13, 256>>>(sb2, qb2, kb2);
    assemble_interp<<<NB, 256>>>(q, p, m, dt, out);
}